// round 1
// baseline (speedup 1.0000x reference)
#include <cuda_runtime.h>
#include <math.h>

#define N_NODES 20000
#define N_EDGES 640000
#define D 256
#define N_RELS 8
#define N_BASES 4

// Scratch (device globals: allocation-free rule)
__device__ float g_C[(size_t)N_NODES * 1280];    // [n, b*256+o] for b<4 ; [n,1024+o] = loop proj
__device__ float g_hall[(size_t)N_NODES * 2048]; // [n, r*256+o]
__device__ float g_agg[(size_t)N_NODES * 256];   // running aggregate (+loop+bias+x)

__device__ __forceinline__ void red_add_v4(float4* addr, float4 v) {
    asm volatile("red.global.add.v4.f32 [%0], {%1,%2,%3,%4};"
                 :: "l"(addr), "f"(v.x), "f"(v.y), "f"(v.z), "f"(v.w) : "memory");
}

__device__ __forceinline__ float gelu_exact(float x) {
    return 0.5f * x * (1.0f + erff(x * 0.70710678118654752440f));
}

// ---------------------------------------------------------------------------
// GEMM: C[M=20000, N=1280] = X[20000,256] @ B[256,1280]
// B columns [0,1024): basis[b,i,o] at n = b*256+o ; [1024,1280): loop_w[i, n-1024]
// 128x128 tile, BK=8, 256 threads, 8x8 per thread.
// ---------------------------------------------------------------------------
__global__ void __launch_bounds__(256, 2) gemm_kernel(const float* __restrict__ X,
                                                      const float* __restrict__ basis,
                                                      const float* __restrict__ loopw) {
    __shared__ float As[8][128];
    __shared__ float Bs[8][128];

    const int tid = threadIdx.x;
    const int m0 = blockIdx.y * 128;
    const int n0 = blockIdx.x * 128;

    const float* Bbase;
    if (n0 < 1024) Bbase = basis + (size_t)(n0 >> 8) * 65536 + (n0 & 255);
    else           Bbase = loopw + (n0 - 1024);

    const int arow = tid >> 1;         // 0..127
    const int akq  = (tid & 1) * 4;    // 0 or 4
    const int brow = tid >> 5;         // 0..7
    const int bcol = (tid & 31) * 4;   // 0..124

    const int ty = tid >> 4;           // 0..15
    const int tx = tid & 15;           // 0..15

    __align__(16) float acc[8][8];
#pragma unroll
    for (int i = 0; i < 8; i++)
#pragma unroll
        for (int j = 0; j < 8; j++) acc[i][j] = 0.0f;

    const int am = m0 + arow;
    const bool avalid = (am < N_NODES);
    const float* aptr = X + (size_t)(avalid ? am : 0) * 256 + akq;
    const float* bptr = Bbase + (size_t)brow * 256 + bcol;

    for (int k0 = 0; k0 < 256; k0 += 8) {
        float4 av = make_float4(0.f, 0.f, 0.f, 0.f);
        if (avalid) av = *(const float4*)(aptr + k0);
        As[akq + 0][arow] = av.x;
        As[akq + 1][arow] = av.y;
        As[akq + 2][arow] = av.z;
        As[akq + 3][arow] = av.w;

        float4 bv = *(const float4*)(bptr + (size_t)k0 * 256);
        *(float4*)&Bs[brow][bcol] = bv;

        __syncthreads();

#pragma unroll
        for (int k = 0; k < 8; k++) {
            __align__(16) float a[8], b[8];
            *(float4*)(a)     = *(const float4*)&As[k][ty * 8];
            *(float4*)(a + 4) = *(const float4*)&As[k][ty * 8 + 4];
            *(float4*)(b)     = *(const float4*)&Bs[k][tx * 8];
            *(float4*)(b + 4) = *(const float4*)&Bs[k][tx * 8 + 4];
#pragma unroll
            for (int i = 0; i < 8; i++)
#pragma unroll
                for (int j = 0; j < 8; j++)
                    acc[i][j] = fmaf(a[i], b[j], acc[i][j]);
        }
        __syncthreads();
    }

#pragma unroll
    for (int i = 0; i < 8; i++) {
        int m = m0 + ty * 8 + i;
        if (m >= N_NODES) break;
        float* crow = g_C + (size_t)m * 1280 + n0 + tx * 8;
        *(float4*)(crow)     = *(const float4*)&acc[i][0];
        *(float4*)(crow + 4) = *(const float4*)&acc[i][4];
    }
}

// ---------------------------------------------------------------------------
// Combine: h_all[n,r,:] = sum_b comp[r,b] * C[n,b,:]
//          agg[n,:] = C[n,loop,:] + bias + x[n,:]   (pre-load for epilogue)
// One block (64 threads, float4 lanes) per node.
// ---------------------------------------------------------------------------
__global__ void __launch_bounds__(64) combine_kernel(const float* __restrict__ x,
                                                     const float* __restrict__ comp,
                                                     const float* __restrict__ bias) {
    __shared__ float cs[N_RELS * N_BASES];
    const int n = blockIdx.x;
    const int t = threadIdx.x;   // 0..63 (float4 lane over D=256)
    if (t < N_RELS * N_BASES) cs[t] = comp[t];
    __syncthreads();

    const float4* Crow = (const float4*)(g_C + (size_t)n * 1280);
    float4 cb[5];
#pragma unroll
    for (int b = 0; b < 5; b++) cb[b] = Crow[b * 64 + t];

    float4* hrow = (float4*)(g_hall + (size_t)n * 2048);
#pragma unroll
    for (int r = 0; r < N_RELS; r++) {
        float4 h = make_float4(0.f, 0.f, 0.f, 0.f);
#pragma unroll
        for (int b = 0; b < N_BASES; b++) {
            float c = cs[r * N_BASES + b];
            h.x = fmaf(c, cb[b].x, h.x);
            h.y = fmaf(c, cb[b].y, h.y);
            h.z = fmaf(c, cb[b].z, h.z);
            h.w = fmaf(c, cb[b].w, h.w);
        }
        hrow[r * 64 + t] = h;
    }

    float4 xv = ((const float4*)x)[(size_t)n * 64 + t];
    float4 bb = ((const float4*)bias)[t];
    float4 lv = cb[4];
    float4 a;
    a.x = lv.x + bb.x + xv.x;
    a.y = lv.y + bb.y + xv.y;
    a.z = lv.z + bb.z + xv.z;
    a.w = lv.w + bb.w + xv.w;
    ((float4*)g_agg)[(size_t)n * 64 + t] = a;
}

// ---------------------------------------------------------------------------
// Scatter: one warp per edge; gather 1KB message row, vector-red into agg.
// agg is 20MB -> fully L2-resident; atomics never reach DRAM.
// ---------------------------------------------------------------------------
__global__ void __launch_bounds__(256) scatter_kernel(const int* __restrict__ src,
                                                      const int* __restrict__ dst,
                                                      const int* __restrict__ et) {
    int gid = blockIdx.x * blockDim.x + threadIdx.x;
    int e = gid >> 5;
    int lane = gid & 31;
    if (e >= N_EDGES) return;
    int s = __ldg(src + e);
    int d = __ldg(dst + e);
    int t = __ldg(et + e);

    const float4* row = (const float4*)(g_hall + (size_t)s * 2048 + (size_t)t * 256);
    float4* arow = (float4*)(g_agg + (size_t)d * 256);

    float4 v0 = row[lane];
    float4 v1 = row[lane + 32];
    red_add_v4(arow + lane, v0);
    red_add_v4(arow + lane + 32, v1);
}

// ---------------------------------------------------------------------------
// Epilogue: warp per node. h = gelu(agg) ; LayerNorm(h)*gamma + beta
// (agg already contains messages + loop + bias + residual x)
// ---------------------------------------------------------------------------
__global__ void __launch_bounds__(256) epilogue_kernel(const float* __restrict__ gamma,
                                                       const float* __restrict__ beta,
                                                       float* __restrict__ out) {
    int gid = blockIdx.x * blockDim.x + threadIdx.x;
    int n = gid >> 5;
    int lane = gid & 31;
    if (n >= N_NODES) return;

    const float4* arow = (const float4*)(g_agg + (size_t)n * 256);
    float4 t0 = arow[lane];
    float4 t1 = arow[lane + 32];

    float h[8];
    h[0] = gelu_exact(t0.x); h[1] = gelu_exact(t0.y);
    h[2] = gelu_exact(t0.z); h[3] = gelu_exact(t0.w);
    h[4] = gelu_exact(t1.x); h[5] = gelu_exact(t1.y);
    h[6] = gelu_exact(t1.z); h[7] = gelu_exact(t1.w);

    float s = 0.f;
#pragma unroll
    for (int i = 0; i < 8; i++) s += h[i];
#pragma unroll
    for (int off = 16; off > 0; off >>= 1) s += __shfl_xor_sync(0xffffffffu, s, off);
    float mu = s * (1.0f / 256.0f);

    float v = 0.f;
#pragma unroll
    for (int i = 0; i < 8; i++) {
        float dlt = h[i] - mu;
        v = fmaf(dlt, dlt, v);
    }
#pragma unroll
    for (int off = 16; off > 0; off >>= 1) v += __shfl_xor_sync(0xffffffffu, v, off);
    float inv = rsqrtf(v * (1.0f / 256.0f) + 1e-5f);

    float4 g0 = ((const float4*)gamma)[lane];
    float4 g1 = ((const float4*)gamma)[lane + 32];
    float4 b0 = ((const float4*)beta)[lane];
    float4 b1 = ((const float4*)beta)[lane + 32];

    float4 o0, o1;
    o0.x = (h[0] - mu) * inv * g0.x + b0.x;
    o0.y = (h[1] - mu) * inv * g0.y + b0.y;
    o0.z = (h[2] - mu) * inv * g0.z + b0.z;
    o0.w = (h[3] - mu) * inv * g0.w + b0.w;
    o1.x = (h[4] - mu) * inv * g1.x + b1.x;
    o1.y = (h[5] - mu) * inv * g1.y + b1.y;
    o1.z = (h[6] - mu) * inv * g1.z + b1.z;
    o1.w = (h[7] - mu) * inv * g1.w + b1.w;

    float4* orow = (float4*)(out + (size_t)n * 256);
    orow[lane] = o0;
    orow[lane + 32] = o1;
}

extern "C" void kernel_launch(void* const* d_in, const int* in_sizes, int n_in,
                              void* d_out, int out_size) {
    const float* x     = (const float*)d_in[0];
    const int*   src   = (const int*)  d_in[1];
    const int*   dst   = (const int*)  d_in[2];
    const int*   et    = (const int*)  d_in[3];
    const float* basis = (const float*)d_in[4];
    const float* comp  = (const float*)d_in[5];
    const float* loopw = (const float*)d_in[6];
    const float* bias  = (const float*)d_in[7];
    const float* gamma = (const float*)d_in[8];
    const float* beta  = (const float*)d_in[9];
    float* out = (float*)d_out;

    dim3 gg(10, 157);   // N=1280/128, M=ceil(20000/128)
    gemm_kernel<<<gg, 256>>>(x, basis, loopw);
    combine_kernel<<<N_NODES, 64>>>(x, comp, bias);
    scatter_kernel<<<(N_EDGES * 32) / 256, 256>>>(src, dst, et);
    epilogue_kernel<<<(N_NODES * 32) / 256, 256>>>(gamma, beta, out);
}

// round 3
// speedup vs baseline: 1.4000x; 1.4000x over previous
#include <cuda_runtime.h>
#include <cuda_bf16.h>
#include <math.h>
#include <cstdint>

#define N_NODES 20000
#define N_EDGES 640000
#define D 256
#define N_RELS 8
#define N_BASES 4
#define KSPLIT 768           // [hi | lo | hi] along K
#define NCOLS 1280           // 4 basis blocks (1024) + loop (256)

// ---------------- device scratch (allocation-free rule) ----------------
__device__ __align__(16) __nv_bfloat16 g_A3[(size_t)N_NODES * KSPLIT];   // 30.7MB
__device__ __align__(16) __nv_bfloat16 g_Bt[(size_t)NCOLS * KSPLIT];     // 1.9MB  [n][k]
__device__ float g_C[(size_t)N_NODES * NCOLS];     // GEMM out
__device__ float g_hall[(size_t)N_NODES * 2048];   // [n, r*256+o]
__device__ float g_agg[(size_t)N_NODES * 256];

__device__ __forceinline__ void red_add_v4(float4* addr, float4 v) {
    asm volatile("red.global.add.v4.f32 [%0], {%1,%2,%3,%4};"
                 :: "l"(addr), "f"(v.x), "f"(v.y), "f"(v.z), "f"(v.w) : "memory");
}
__device__ __forceinline__ float gelu_exact(float x) {
    return 0.5f * x * (1.0f + erff(x * 0.70710678118654752440f));
}
__device__ __forceinline__ uint32_t smem_to_u32(const void* p) {
    uint32_t a;
    asm("{ .reg .u64 t; cvta.to.shared.u64 t, %1; cvt.u32.u64 %0, t; }" : "=r"(a) : "l"(p));
    return a;
}
__device__ __forceinline__ void cp_async16(uint32_t dst, const void* src, int src_sz) {
    asm volatile("cp.async.cg.shared.global [%0], [%1], 16, %2;" :: "r"(dst), "l"(src), "r"(src_sz) : "memory");
}
__device__ __forceinline__ void cp_async_commit() { asm volatile("cp.async.commit_group;" ::: "memory"); }
template <int N> __device__ __forceinline__ void cp_async_wait() {
    asm volatile("cp.async.wait_group %0;" :: "n"(N) : "memory");
}
__device__ __forceinline__ void ldsm_x4(uint32_t& r0, uint32_t& r1, uint32_t& r2, uint32_t& r3, uint32_t addr) {
    asm volatile("ldmatrix.sync.aligned.m8n8.x4.shared.b16 {%0,%1,%2,%3}, [%4];"
                 : "=r"(r0), "=r"(r1), "=r"(r2), "=r"(r3) : "r"(addr));
}
__device__ __forceinline__ void mma16816(float* d, uint32_t a0, uint32_t a1, uint32_t a2, uint32_t a3,
                                         uint32_t b0, uint32_t b1) {
    asm volatile("mma.sync.aligned.m16n8k16.row.col.f32.bf16.bf16.f32 "
                 "{%0,%1,%2,%3}, {%4,%5,%6,%7}, {%8,%9}, {%0,%1,%2,%3};"
                 : "+f"(d[0]), "+f"(d[1]), "+f"(d[2]), "+f"(d[3])
                 : "r"(a0), "r"(a1), "r"(a2), "r"(a3), "r"(b0), "r"(b1));
}

// ---------------------------------------------------------------------------
// Prep 1: split x -> A3 = [hi | lo | hi] bf16
// ---------------------------------------------------------------------------
__global__ void __launch_bounds__(256) split_x_kernel(const float* __restrict__ x) {
    int gid = blockIdx.x * blockDim.x + threadIdx.x;   // one per 4 elems
    if (gid >= N_NODES * 64) return;
    int m = gid >> 6;
    int k4 = (gid & 63) * 4;
    float4 v = *(const float4*)(x + (size_t)m * 256 + k4);
    __nv_bfloat162 hi01, hi23, lo01, lo23;
    float h;
    h = __bfloat162float(__float2bfloat16(v.x)); hi01.x = __float2bfloat16(v.x); lo01.x = __float2bfloat16(v.x - h);
    h = __bfloat162float(__float2bfloat16(v.y)); hi01.y = __float2bfloat16(v.y); lo01.y = __float2bfloat16(v.y - h);
    h = __bfloat162float(__float2bfloat16(v.z)); hi23.x = __float2bfloat16(v.z); lo23.x = __float2bfloat16(v.z - h);
    h = __bfloat162float(__float2bfloat16(v.w)); hi23.y = __float2bfloat16(v.w); lo23.y = __float2bfloat16(v.w - h);
    __nv_bfloat162* row = (__nv_bfloat162*)(g_A3 + (size_t)m * KSPLIT);
    row[(k4 >> 1) + 0] = hi01;  row[(k4 >> 1) + 1] = hi23;            // hi block
    row[128 + (k4 >> 1) + 0] = lo01; row[128 + (k4 >> 1) + 1] = lo23; // lo block
    row[256 + (k4 >> 1) + 0] = hi01; row[256 + (k4 >> 1) + 1] = hi23; // hi block again
}

// ---------------------------------------------------------------------------
// Prep 2: Bt[n][0:256]=W_hi, [256:512]=W_hi, [512:768]=W_lo  (bf16)
// W[k][n] = basis[n>>8][k][n&255]  (n<1024)  else loop_w[k][n-1024]
// ---------------------------------------------------------------------------
__global__ void __launch_bounds__(256) prep_b_kernel(const float* __restrict__ basis,
                                                     const float* __restrict__ loopw) {
    int n = blockIdx.x;     // 0..1279
    int k = threadIdx.x;    // 0..255
    float w;
    if (n < 1024) w = basis[(size_t)(n >> 8) * 65536 + (size_t)k * 256 + (n & 255)];
    else          w = loopw[(size_t)k * 256 + (n - 1024)];
    __nv_bfloat16 hi = __float2bfloat16(w);
    __nv_bfloat16 lo = __float2bfloat16(w - __bfloat162float(hi));
    __nv_bfloat16* row = g_Bt + (size_t)n * KSPLIT;
    row[k] = hi; row[256 + k] = hi; row[512 + k] = lo;
}

// ---------------------------------------------------------------------------
// bf16 mma.sync GEMM: C[20000,1280] = A3[20000,768] @ Bt^T
// CTA tile 128x128, K-chunk 32, double-buffered cp.async, 256 threads (8 warps)
// warp tile 32x64 = 2(m16) x 8(n8) mma frags
// ---------------------------------------------------------------------------
#define KCH 32
#define NCH (KSPLIT / KCH)      // 24
#define ROWB 80                 // 32 bf16 = 64B data + 16B pad (conflict-free ldmatrix)
#define TILE_B (128 * ROWB)     // 10240

__global__ void __launch_bounds__(256) gemm_mma_kernel() {
    __shared__ __align__(16) char sA[2][TILE_B];
    __shared__ __align__(16) char sB[2][TILE_B];

    const int tid = threadIdx.x;
    const int lane = tid & 31;
    const int wid = tid >> 5;
    const int warp_m = wid & 3;   // 0..3 -> rows 32*warp_m
    const int warp_n = wid >> 2;  // 0..1 -> cols 64*warp_n
    const int m0 = blockIdx.y * 128;
    const int n0 = blockIdx.x * 128;

    const uint32_t sAu[2] = { smem_to_u32(sA[0]), smem_to_u32(sA[1]) };
    const uint32_t sBu[2] = { smem_to_u32(sB[0]), smem_to_u32(sB[1]) };

    // per-thread gmem->smem mapping: row = tid>>1, 2x16B at (tid&1)*32
    const int ldr = tid >> 1;
    const int ldc = (tid & 1) * 32;              // byte offset within 64B row data
    const int am = m0 + ldr;
    const int asz = (am < N_NODES) ? 16 : 0;
    const __nv_bfloat16* aRow = g_A3 + (size_t)am * KSPLIT + (ldc >> 1);
    const __nv_bfloat16* bRow = g_Bt + (size_t)(n0 + ldr) * KSPLIT + (ldc >> 1);
    const uint32_t aDst = ldr * ROWB + ldc;
    const uint32_t bDst = ldr * ROWB + ldc;

    auto load_chunk = [&](int c, int s) {
        int k0 = c * KCH;
        cp_async16(sAu[s] + aDst,      aRow + k0,     asz);
        cp_async16(sAu[s] + aDst + 16, aRow + k0 + 8, asz);
        cp_async16(sBu[s] + bDst,      bRow + k0,     16);
        cp_async16(sBu[s] + bDst + 16, bRow + k0 + 8, 16);
        cp_async_commit();
    };

    float acc[2][8][4];
#pragma unroll
    for (int i = 0; i < 2; i++)
#pragma unroll
        for (int t = 0; t < 8; t++)
#pragma unroll
            for (int q = 0; q < 4; q++) acc[i][t][q] = 0.0f;

    // ldmatrix address offsets (within a buffer)
    // A frag (m16 tile i, k-step kk): row = warp_m*32 + i*16 + lane%16 ; colb = (kk + (lane/16)*8)*2
    const uint32_t aLd = (warp_m * 32 + (lane & 15)) * ROWB + (lane >> 4) * 16;
    // B frag (n8 pair j, k-step kk): row = warp_n*64 + j*16 + 8*(lane/16) + lane%8 ; colb = (kk + 8*((lane/8)&1))*2
    const uint32_t bLd = (warp_n * 64 + ((lane >> 4) << 3) + (lane & 7)) * ROWB + (((lane >> 3) & 1) << 4);

    load_chunk(0, 0);
    for (int c = 0; c < NCH; c++) {
        if (c + 1 < NCH) load_chunk(c + 1, (c + 1) & 1);
        if (c + 1 < NCH) cp_async_wait<1>(); else cp_async_wait<0>();
        __syncthreads();

        const int s = c & 1;
#pragma unroll
        for (int kk = 0; kk < 2; kk++) {       // two k16 steps in 32-chunk
            uint32_t a[2][4];
#pragma unroll
            for (int i = 0; i < 2; i++)
                ldsm_x4(a[i][0], a[i][1], a[i][2], a[i][3],
                        sAu[s] + aLd + i * 16 * ROWB + kk * 32);
            uint32_t b[4][4];
#pragma unroll
            for (int j = 0; j < 4; j++)
                ldsm_x4(b[j][0], b[j][1], b[j][2], b[j][3],
                        sBu[s] + bLd + j * 16 * ROWB + kk * 32);
#pragma unroll
            for (int i = 0; i < 2; i++)
#pragma unroll
                for (int t = 0; t < 8; t++)
                    mma16816(acc[i][t], a[i][0], a[i][1], a[i][2], a[i][3],
                             b[t >> 1][(t & 1) * 2], b[t >> 1][(t & 1) * 2 + 1]);
        }
        __syncthreads();
    }

    // epilogue: d-frag (row = l/4 [+8], col = (l%4)*2)
    const int colBase = n0 + warp_n * 64 + (lane & 3) * 2;
#pragma unroll
    for (int i = 0; i < 2; i++) {
        int r0 = m0 + warp_m * 32 + i * 16 + (lane >> 2);
#pragma unroll
        for (int half = 0; half < 2; half++) {
            int r = r0 + half * 8;
            if (r < N_NODES) {
                float* crow = g_C + (size_t)r * NCOLS;
#pragma unroll
                for (int t = 0; t < 8; t++) {
                    float2 v = make_float2(acc[i][t][half * 2], acc[i][t][half * 2 + 1]);
                    *(float2*)(crow + colBase + t * 8) = v;
                }
            }
        }
    }
}

// ---------------------------------------------------------------------------
// Combine: h_all[n,r,:] = sum_b comp[r,b] * C[n,b,:]
//          agg[n,:] = C[n,loop,:] + bias + x[n,:]
// ---------------------------------------------------------------------------
__global__ void __launch_bounds__(64) combine_kernel(const float* __restrict__ x,
                                                     const float* __restrict__ comp,
                                                     const float* __restrict__ bias) {
    __shared__ float cs[N_RELS * N_BASES];
    const int n = blockIdx.x;
    const int t = threadIdx.x;
    if (t < N_RELS * N_BASES) cs[t] = comp[t];
    __syncthreads();

    const float4* Crow = (const float4*)(g_C + (size_t)n * NCOLS);
    float4 cb[5];
#pragma unroll
    for (int b = 0; b < 5; b++) cb[b] = Crow[b * 64 + t];

    float4* hrow = (float4*)(g_hall + (size_t)n * 2048);
#pragma unroll
    for (int r = 0; r < N_RELS; r++) {
        float4 h = make_float4(0.f, 0.f, 0.f, 0.f);
#pragma unroll
        for (int b = 0; b < N_BASES; b++) {
            float c = cs[r * N_BASES + b];
            h.x = fmaf(c, cb[b].x, h.x);
            h.y = fmaf(c, cb[b].y, h.y);
            h.z = fmaf(c, cb[b].z, h.z);
            h.w = fmaf(c, cb[b].w, h.w);
        }
        hrow[r * 64 + t] = h;
    }

    float4 xv = ((const float4*)x)[(size_t)n * 64 + t];
    float4 bb = ((const float4*)bias)[t];
    float4 lv = cb[4];
    float4 a;
    a.x = lv.x + bb.x + xv.x;
    a.y = lv.y + bb.y + xv.y;
    a.z = lv.z + bb.z + xv.z;
    a.w = lv.w + bb.w + xv.w;
    ((float4*)g_agg)[(size_t)n * 64 + t] = a;
}

// ---------------------------------------------------------------------------
// Scatter: one warp per edge
// ---------------------------------------------------------------------------
__global__ void __launch_bounds__(256) scatter_kernel(const int* __restrict__ src,
                                                      const int* __restrict__ dst,
                                                      const int* __restrict__ et) {
    int gid = blockIdx.x * blockDim.x + threadIdx.x;
    int e = gid >> 5;
    int lane = gid & 31;
    if (e >= N_EDGES) return;
    int s = __ldg(src + e);
    int d = __ldg(dst + e);
    int t = __ldg(et + e);

    const float4* row = (const float4*)(g_hall + (size_t)s * 2048 + (size_t)t * 256);
    float4* arow = (float4*)(g_agg + (size_t)d * 256);

    float4 v0 = row[lane];
    float4 v1 = row[lane + 32];
    red_add_v4(arow + lane, v0);
    red_add_v4(arow + lane + 32, v1);
}

// ---------------------------------------------------------------------------
// Epilogue: GELU + LayerNorm
// ---------------------------------------------------------------------------
__global__ void __launch_bounds__(256) epilogue_kernel(const float* __restrict__ gamma,
                                                       const float* __restrict__ beta,
                                                       float* __restrict__ out) {
    int gid = blockIdx.x * blockDim.x + threadIdx.x;
    int n = gid >> 5;
    int lane = gid & 31;
    if (n >= N_NODES) return;

    const float4* arow = (const float4*)(g_agg + (size_t)n * 256);
    float4 t0 = arow[lane];
    float4 t1 = arow[lane + 32];

    float h[8];
    h[0] = gelu_exact(t0.x); h[1] = gelu_exact(t0.y);
    h[2] = gelu_exact(t0.z); h[3] = gelu_exact(t0.w);
    h[4] = gelu_exact(t1.x); h[5] = gelu_exact(t1.y);
    h[6] = gelu_exact(t1.z); h[7] = gelu_exact(t1.w);

    float s = 0.f;
#pragma unroll
    for (int i = 0; i < 8; i++) s += h[i];
#pragma unroll
    for (int off = 16; off > 0; off >>= 1) s += __shfl_xor_sync(0xffffffffu, s, off);
    float mu = s * (1.0f / 256.0f);

    float v = 0.f;
#pragma unroll
    for (int i = 0; i < 8; i++) {
        float dlt = h[i] - mu;
        v = fmaf(dlt, dlt, v);
    }
#pragma unroll
    for (int off = 16; off > 0; off >>= 1) v += __shfl_xor_sync(0xffffffffu, v, off);
    float inv = rsqrtf(v * (1.0f / 256.0f) + 1e-5f);

    float4 g0 = ((const float4*)gamma)[lane];
    float4 g1 = ((const float4*)gamma)[lane + 32];
    float4 b0 = ((const float4*)beta)[lane];
    float4 b1 = ((const float4*)beta)[lane + 32];

    float4 o0, o1;
    o0.x = (h[0] - mu) * inv * g0.x + b0.x;
    o0.y = (h[1] - mu) * inv * g0.y + b0.y;
    o0.z = (h[2] - mu) * inv * g0.z + b0.z;
    o0.w = (h[3] - mu) * inv * g0.w + b0.w;
    o1.x = (h[4] - mu) * inv * g1.x + b1.x;
    o1.y = (h[5] - mu) * inv * g1.y + b1.y;
    o1.z = (h[6] - mu) * inv * g1.z + b1.z;
    o1.w = (h[7] - mu) * inv * g1.w + b1.w;

    float4* orow = (float4*)(out + (size_t)n * 256);
    orow[lane] = o0;
    orow[lane + 32] = o1;
}

extern "C" void kernel_launch(void* const* d_in, const int* in_sizes, int n_in,
                              void* d_out, int out_size) {
    const float* x     = (const float*)d_in[0];
    const int*   src   = (const int*)  d_in[1];
    const int*   dst   = (const int*)  d_in[2];
    const int*   et    = (const int*)  d_in[3];
    const float* basis = (const float*)d_in[4];
    const float* comp  = (const float*)d_in[5];
    const float* loopw = (const float*)d_in[6];
    const float* bias  = (const float*)d_in[7];
    const float* gamma = (const float*)d_in[8];
    const float* beta  = (const float*)d_in[9];
    float* out = (float*)d_out;

    split_x_kernel<<<(N_NODES * 64 + 255) / 256, 256>>>(x);
    prep_b_kernel<<<NCOLS, 256>>>(basis, loopw);
    dim3 gg(10, 157);
    gemm_mma_kernel<<<gg, 256>>>();
    combine_kernel<<<N_NODES, 64>>>(x, comp, bias);
    scatter_kernel<<<(N_EDGES * 32) / 256, 256>>>(src, dst, et);
    epilogue_kernel<<<(N_NODES * 32) / 256, 256>>>(gamma, beta, out);
}

// round 7
// speedup vs baseline: 1.7190x; 1.2279x over previous
#include <cuda_runtime.h>
#include <cuda_bf16.h>
#include <math.h>
#include <cstdint>

#define N_NODES 20000
#define N_EDGES 640000
#define D 256
#define N_RELS 8
#define N_BASES 4
#define KTOT 3840            // [T_hi(1024)|T_lo(1024)|T_hi(1024)|x_hi(256)|x_lo(256)|x_hi(256)]
#define KSEG 1280            // 3 K-segments for GEMM load balance

// ---------------- device scratch (allocation-free rule) ----------------
__device__ __align__(16) __nv_bfloat16 g_A3[(size_t)N_NODES * KTOT];  // 154MB
__device__ __align__(16) __nv_bfloat16 g_B2[(size_t)256 * KTOT];      // 1.9MB [out-col n][k]
__device__ float g_agg[(size_t)N_NODES * 256];                        // 20MB
__device__ int g_hist[N_NODES];
__device__ int g_cursor[N_NODES];
__device__ int g_start[N_NODES + 1];
__device__ uint32_t g_edges[N_EDGES];   // packed src | (type<<15)

__device__ __forceinline__ float gelu_exact(float x) {
    return 0.5f * x * (1.0f + erff(x * 0.70710678118654752440f));
}
__device__ __forceinline__ uint32_t smem_to_u32(const void* p) {
    uint32_t a;
    asm("{ .reg .u64 t; cvta.to.shared.u64 t, %1; cvt.u32.u64 %0, t; }" : "=r"(a) : "l"(p));
    return a;
}
__device__ __forceinline__ void cp_async16(uint32_t dst, const void* src, int src_sz) {
    asm volatile("cp.async.cg.shared.global [%0], [%1], 16, %2;" :: "r"(dst), "l"(src), "r"(src_sz) : "memory");
}
__device__ __forceinline__ void cp_async_commit() { asm volatile("cp.async.commit_group;" ::: "memory"); }
template <int N> __device__ __forceinline__ void cp_async_wait() {
    asm volatile("cp.async.wait_group %0;" :: "n"(N) : "memory");
}
__device__ __forceinline__ void ldsm_x4(uint32_t& r0, uint32_t& r1, uint32_t& r2, uint32_t& r3, uint32_t addr) {
    asm volatile("ldmatrix.sync.aligned.m8n8.x4.shared.b16 {%0,%1,%2,%3}, [%4];"
                 : "=r"(r0), "=r"(r1), "=r"(r2), "=r"(r3) : "r"(addr));
}
__device__ __forceinline__ void mma16816(float* d, uint32_t a0, uint32_t a1, uint32_t a2, uint32_t a3,
                                         uint32_t b0, uint32_t b1) {
    asm volatile("mma.sync.aligned.m16n8k16.row.col.f32.bf16.bf16.f32 "
                 "{%0,%1,%2,%3}, {%4,%5,%6,%7}, {%8,%9}, {%0,%1,%2,%3};"
                 : "+f"(d[0]), "+f"(d[1]), "+f"(d[2]), "+f"(d[3])
                 : "r"(a0), "r"(a1), "r"(a2), "r"(a3), "r"(b0), "r"(b1));
}
__device__ __forceinline__ void red_add_v2(float* addr, float a, float b) {
    asm volatile("red.global.add.v2.f32 [%0], {%1,%2};" :: "l"(addr), "f"(a), "f"(b) : "memory");
}

// ---------------------------------------------------------------------------
// Zero: g_agg (1.28M float4) + g_hist
// ---------------------------------------------------------------------------
__global__ void __launch_bounds__(256) zero_kernel() {
    int gid = blockIdx.x * blockDim.x + threadIdx.x;
    if (gid < N_NODES * 64) ((float4*)g_agg)[gid] = make_float4(0.f, 0.f, 0.f, 0.f);
    if (gid < N_NODES) g_hist[gid] = 0;
}

__global__ void __launch_bounds__(256) hist_kernel(const int* __restrict__ dst) {
    int e = blockIdx.x * blockDim.x + threadIdx.x;
    if (e < N_EDGES) atomicAdd(&g_hist[dst[e]], 1);
}

// single block 1024 threads, 20 bins each
__global__ void __launch_bounds__(1024) scan_kernel() {
    __shared__ int sm[1024];
    int t = threadIdx.x;
    int base = t * 20;
    int cnt[20];
    int s = 0;
#pragma unroll
    for (int i = 0; i < 20; i++) {
        int idx = base + i;
        int c = (idx < N_NODES) ? g_hist[idx] : 0;
        cnt[i] = c; s += c;
    }
    sm[t] = s;
    __syncthreads();
    for (int off = 1; off < 1024; off <<= 1) {
        int v = (t >= off) ? sm[t - off] : 0;
        __syncthreads();
        sm[t] += v;
        __syncthreads();
    }
    int run = (t > 0) ? sm[t - 1] : 0;
#pragma unroll
    for (int i = 0; i < 20; i++) {
        int idx = base + i;
        if (idx < N_NODES) {
            g_start[idx] = run;
            g_cursor[idx] = run;
            run += cnt[i];
        }
    }
    if (t == 1023) g_start[N_NODES] = sm[1023];
}

__global__ void __launch_bounds__(256) reorder_kernel(const int* __restrict__ src,
                                                      const int* __restrict__ dst,
                                                      const int* __restrict__ et) {
    int e = blockIdx.x * blockDim.x + threadIdx.x;
    if (e >= N_EDGES) return;
    int d = dst[e];
    int pos = atomicAdd(&g_cursor[d], 1);
    g_edges[pos] = (uint32_t)src[e] | ((uint32_t)et[e] << 15);
}

// ---------------------------------------------------------------------------
// Prep B2: [out-col n][k] bf16.
// k<3072: T part: blk=k>>10, kk=k&1023, b=kk>>8, i=kk&255 -> basis[b][i][n]; blk<2 hi else lo
// k>=3072: loop part: kk=k-3072, blk=kk>>8, i=kk&255 -> loop_w[i][n]; blk<2 hi else lo
// ---------------------------------------------------------------------------
__global__ void __launch_bounds__(256) prep_b2_kernel(const float* __restrict__ basis,
                                                      const float* __restrict__ loopw) {
    int n = blockIdx.x;   // 0..255
    for (int k = threadIdx.x; k < KTOT; k += 256) {
        float w; int blk;
        if (k < 3072) {
            blk = k >> 10;
            int kk = k & 1023;
            int b = kk >> 8, i = kk & 255;
            w = basis[(size_t)b * 65536 + (size_t)i * 256 + n];
        } else {
            int kk = k - 3072;
            blk = kk >> 8;
            int i = kk & 255;
            w = loopw[(size_t)i * 256 + n];
        }
        __nv_bfloat16 hi = __float2bfloat16(w);
        __nv_bfloat16 out = (blk < 2) ? hi : __float2bfloat16(w - __bfloat162float(hi));
        g_B2[(size_t)n * KTOT + k] = out;
    }
}

// ---------------------------------------------------------------------------
// Fused gather + aggregate + combine + split: one warp per node.
// accT[b][j] = sum over incident edges of comp[type][b] * x[src][lane*8+j]
// then write A3 row [T_hi|T_lo|T_hi|x_hi|x_lo|x_hi] (bf16)
// ---------------------------------------------------------------------------
__device__ __forceinline__ void split8_store(__nv_bfloat16* rowbase, int off_hi1, int off_lo,
                                             int off_hi2, const float* v) {
    union { __nv_bfloat162 h2[4]; uint4 u; } phi, plo;
#pragma unroll
    for (int q = 0; q < 4; q++) {
        float a = v[q * 2], b = v[q * 2 + 1];
        __nv_bfloat16 ha = __float2bfloat16(a), hb = __float2bfloat16(b);
        __nv_bfloat16 la = __float2bfloat16(a - __bfloat162float(ha));
        __nv_bfloat16 lb = __float2bfloat16(b - __bfloat162float(hb));
        phi.h2[q] = __nv_bfloat162(ha, hb);
        plo.h2[q] = __nv_bfloat162(la, lb);
    }
    *(uint4*)(rowbase + off_hi1) = phi.u;
    *(uint4*)(rowbase + off_lo)  = plo.u;
    *(uint4*)(rowbase + off_hi2) = phi.u;
}

__global__ void __launch_bounds__(256) agg_kernel(const float* __restrict__ x,
                                                  const float* __restrict__ comp) {
    __shared__ float4 cs4[N_RELS];
    int tid = threadIdx.x;
    if (tid < N_RELS)
        cs4[tid] = make_float4(comp[tid * 4 + 0], comp[tid * 4 + 1], comp[tid * 4 + 2], comp[tid * 4 + 3]);
    __syncthreads();

    int v = blockIdx.x * 8 + (tid >> 5);
    int lane = tid & 31;
    if (v >= N_NODES) return;

    int s0 = g_start[v];
    int s1 = g_start[v + 1];
    int c0 = lane * 8;

    float accT[4][8];
#pragma unroll
    for (int b = 0; b < 4; b++)
#pragma unroll
        for (int j = 0; j < 8; j++) accT[b][j] = 0.f;

    auto accum = [&](uint32_t p, float4 xa, float4 xb) {
        float4 cv = cs4[p >> 15];
        float c;
        c = cv.x;
        accT[0][0] += c * xa.x; accT[0][1] += c * xa.y; accT[0][2] += c * xa.z; accT[0][3] += c * xa.w;
        accT[0][4] += c * xb.x; accT[0][5] += c * xb.y; accT[0][6] += c * xb.z; accT[0][7] += c * xb.w;
        c = cv.y;
        accT[1][0] += c * xa.x; accT[1][1] += c * xa.y; accT[1][2] += c * xa.z; accT[1][3] += c * xa.w;
        accT[1][4] += c * xb.x; accT[1][5] += c * xb.y; accT[1][6] += c * xb.z; accT[1][7] += c * xb.w;
        c = cv.z;
        accT[2][0] += c * xa.x; accT[2][1] += c * xa.y; accT[2][2] += c * xa.z; accT[2][3] += c * xa.w;
        accT[2][4] += c * xb.x; accT[2][5] += c * xb.y; accT[2][6] += c * xb.z; accT[2][7] += c * xb.w;
        c = cv.w;
        accT[3][0] += c * xa.x; accT[3][1] += c * xa.y; accT[3][2] += c * xa.z; accT[3][3] += c * xa.w;
        accT[3][4] += c * xb.x; accT[3][5] += c * xb.y; accT[3][6] += c * xb.z; accT[3][7] += c * xb.w;
    };

    int e = s0;
    for (; e + 4 <= s1; e += 4) {
        uint32_t p[4];
        float4 xa[4], xb[4];
#pragma unroll
        for (int j = 0; j < 4; j++) p[j] = __ldg(&g_edges[e + j]);
#pragma unroll
        for (int j = 0; j < 4; j++) {
            const float4* xr = (const float4*)(x + (size_t)(p[j] & 32767) * 256 + c0);
            xa[j] = __ldg(xr);
            xb[j] = __ldg(xr + 1);
        }
#pragma unroll
        for (int j = 0; j < 4; j++) accum(p[j], xa[j], xb[j]);
    }
    for (; e < s1; e++) {
        uint32_t p = __ldg(&g_edges[e]);
        const float4* xr = (const float4*)(x + (size_t)(p & 32767) * 256 + c0);
        accum(p, __ldg(xr), __ldg(xr + 1));
    }

    __nv_bfloat16* arow = g_A3 + (size_t)v * KTOT;
#pragma unroll
    for (int b = 0; b < 4; b++) {
        int o = b * 256 + c0;
        split8_store(arow, o, 1024 + o, 2048 + o, accT[b]);
    }
    // x part
    {
        const float4* xr = (const float4*)(x + (size_t)v * 256 + c0);
        float4 xa = __ldg(xr), xb = __ldg(xr + 1);
        float xv[8] = { xa.x, xa.y, xa.z, xa.w, xb.x, xb.y, xb.z, xb.w };
        split8_store(arow, 3072 + c0, 3328 + c0, 3584 + c0, xv);
    }
}

// ---------------------------------------------------------------------------
// GEMM: agg[20000,256] += A3[20000, seg*1280 : +1280] @ B2seg^T
// Tile M=64, N=256 (full), K-chunk 32, double-buffered cp.async, 256 threads.
// 8 warps: warp_m = wid&1 (2 x 32 rows), warp_n = wid>>1 (4 x 64 cols).
// grid = (3 segs, 313 m-tiles). Epilogue red.add.v2 into g_agg.
// ---------------------------------------------------------------------------
#define KCH 32
#define NCH (KSEG / KCH)        // 40
#define ROWB 80
#define A_TILE (64 * ROWB)      // 5120
#define B_TILE (256 * ROWB)     // 20480
#define GEMM_SMEM (2 * A_TILE + 2 * B_TILE)   // 51200

__global__ void __launch_bounds__(256) gemm_mma_kernel() {
    extern __shared__ __align__(16) char dyn[];
    const uint32_t sAu[2] = { smem_to_u32(dyn), smem_to_u32(dyn + A_TILE) };
    const uint32_t sBu[2] = { smem_to_u32(dyn + 2 * A_TILE), smem_to_u32(dyn + 2 * A_TILE + B_TILE) };

    const int tid = threadIdx.x;
    const int lane = tid & 31;
    const int wid = tid >> 5;
    const int warp_m = wid & 1;
    const int warp_n = wid >> 1;
    const int seg = blockIdx.x;
    const int m0 = blockIdx.y * 64;
    const int kseg = seg * KSEG;

    // A loader: 256 chunks (64 rows x 4x16B); one per thread
    const int ar = tid >> 2;
    const int ac = tid & 3;
    const int am = m0 + ar;
    const int asz = (am < N_NODES) ? 16 : 0;
    const __nv_bfloat16* aSrc = g_A3 + (size_t)((am < N_NODES) ? am : 0) * KTOT + kseg + ac * 8;
    const uint32_t aDst = ar * ROWB + ac * 16;

    auto load_chunk = [&](int c, int s) {
        int k0 = c * KCH;
        cp_async16(sAu[s] + aDst, aSrc + k0, asz);
#pragma unroll
        for (int i = 0; i < 4; i++) {
            int cid = tid + i * 256;
            int br = cid >> 2, bc = cid & 3;
            cp_async16(sBu[s] + br * ROWB + bc * 16,
                       g_B2 + (size_t)br * KTOT + kseg + k0 + bc * 8, 16);
        }
        cp_async_commit();
    };

    float acc[2][8][4];
#pragma unroll
    for (int i = 0; i < 2; i++)
#pragma unroll
        for (int t = 0; t < 8; t++)
#pragma unroll
            for (int q = 0; q < 4; q++) acc[i][t][q] = 0.0f;

    const uint32_t aLd = (warp_m * 32 + (lane & 15)) * ROWB + (lane >> 4) * 16;
    const uint32_t bLd = (warp_n * 64 + ((lane >> 4) << 3) + (lane & 7)) * ROWB + (((lane >> 3) & 1) << 4);

    load_chunk(0, 0);
    for (int c = 0; c < NCH; c++) {
        if (c + 1 < NCH) load_chunk(c + 1, (c + 1) & 1);
        if (c + 1 < NCH) cp_async_wait<1>(); else cp_async_wait<0>();
        __syncthreads();
        const int s = c & 1;
#pragma unroll
        for (int kk = 0; kk < 2; kk++) {
            uint32_t a[2][4];
#pragma unroll
            for (int i = 0; i < 2; i++)
                ldsm_x4(a[i][0], a[i][1], a[i][2], a[i][3],
                        sAu[s] + aLd + i * 16 * ROWB + kk * 32);
            uint32_t b[4][4];
#pragma unroll
            for (int j = 0; j < 4; j++)
                ldsm_x4(b[j][0], b[j][1], b[j][2], b[j][3],
                        sBu[s] + bLd + j * 16 * ROWB + kk * 32);
#pragma unroll
            for (int i = 0; i < 2; i++)
#pragma unroll
                for (int t = 0; t < 8; t++)
                    mma16816(acc[i][t], a[i][0], a[i][1], a[i][2], a[i][3],
                             b[t >> 1][(t & 1) * 2], b[t >> 1][(t & 1) * 2 + 1]);
        }
        __syncthreads();
    }

    const int colBase = warp_n * 64 + (lane & 3) * 2;
#pragma unroll
    for (int i = 0; i < 2; i++) {
        int r0 = m0 + warp_m * 32 + i * 16 + (lane >> 2);
#pragma unroll
        for (int half = 0; half < 2; half++) {
            int r = r0 + half * 8;
            if (r < N_NODES) {
                float* arow = g_agg + (size_t)r * 256;
#pragma unroll
                for (int t = 0; t < 8; t++)
                    red_add_v2(arow + colBase + t * 8, acc[i][t][half * 2], acc[i][t][half * 2 + 1]);
            }
        }
    }
}

// ---------------------------------------------------------------------------
// Epilogue: h = gelu(agg + bias + x); out = LN(h)*gamma + beta
// ---------------------------------------------------------------------------
__global__ void __launch_bounds__(256) epilogue_kernel(const float* __restrict__ x,
                                                       const float* __restrict__ bias,
                                                       const float* __restrict__ gamma,
                                                       const float* __restrict__ beta,
                                                       float* __restrict__ out) {
    int gid = blockIdx.x * blockDim.x + threadIdx.x;
    int n = gid >> 5;
    int lane = gid & 31;
    if (n >= N_NODES) return;

    const float4* arow = (const float4*)(g_agg + (size_t)n * 256);
    const float4* xrow = (const float4*)(x + (size_t)n * 256);
    float4 t0 = arow[lane], t1 = arow[lane + 32];
    float4 x0 = xrow[lane], x1 = xrow[lane + 32];
    float4 bb0 = ((const float4*)bias)[lane];
    float4 bb1 = ((const float4*)bias)[lane + 32];

    float h[8];
    h[0] = gelu_exact(t0.x + bb0.x + x0.x);
    h[1] = gelu_exact(t0.y + bb0.y + x0.y);
    h[2] = gelu_exact(t0.z + bb0.z + x0.z);
    h[3] = gelu_exact(t0.w + bb0.w + x0.w);
    h[4] = gelu_exact(t1.x + bb1.x + x1.x);
    h[5] = gelu_exact(t1.y + bb1.y + x1.y);
    h[6] = gelu_exact(t1.z + bb1.z + x1.z);
    h[7] = gelu_exact(t1.w + bb1.w + x1.w);

    float s = 0.f;
#pragma unroll
    for (int i = 0; i < 8; i++) s += h[i];
#pragma unroll
    for (int off = 16; off > 0; off >>= 1) s += __shfl_xor_sync(0xffffffffu, s, off);
    float mu = s * (1.0f / 256.0f);

    float v = 0.f;
#pragma unroll
    for (int i = 0; i < 8; i++) {
        float dlt = h[i] - mu;
        v = fmaf(dlt, dlt, v);
    }
#pragma unroll
    for (int off = 16; off > 0; off >>= 1) v += __shfl_xor_sync(0xffffffffu, v, off);
    float inv = rsqrtf(v * (1.0f / 256.0f) + 1e-5f);

    float4 g0 = ((const float4*)gamma)[lane];
    float4 g1 = ((const float4*)gamma)[lane + 32];
    float4 b0 = ((const float4*)beta)[lane];
    float4 b1 = ((const float4*)beta)[lane + 32];

    float4 o0, o1;
    o0.x = (h[0] - mu) * inv * g0.x + b0.x;
    o0.y = (h[1] - mu) * inv * g0.y + b0.y;
    o0.z = (h[2] - mu) * inv * g0.z + b0.z;
    o0.w = (h[3] - mu) * inv * g0.w + b0.w;
    o1.x = (h[4] - mu) * inv * g1.x + b1.x;
    o1.y = (h[5] - mu) * inv * g1.y + b1.y;
    o1.z = (h[6] - mu) * inv * g1.z + b1.z;
    o1.w = (h[7] - mu) * inv * g1.w + b1.w;

    float4* orow = (float4*)(out + (size_t)n * 256);
    orow[lane] = o0;
    orow[lane + 32] = o1;
}

extern "C" void kernel_launch(void* const* d_in, const int* in_sizes, int n_in,
                              void* d_out, int out_size) {
    const float* x     = (const float*)d_in[0];
    const int*   src   = (const int*)  d_in[1];
    const int*   dst   = (const int*)  d_in[2];
    const int*   et    = (const int*)  d_in[3];
    const float* basis = (const float*)d_in[4];
    const float* comp  = (const float*)d_in[5];
    const float* loopw = (const float*)d_in[6];
    const float* bias  = (const float*)d_in[7];
    const float* gamma = (const float*)d_in[8];
    const float* beta  = (const float*)d_in[9];
    float* out = (float*)d_out;

    static bool attr_set = false;
    if (!attr_set) {
        cudaFuncSetAttribute(gemm_mma_kernel, cudaFuncAttributeMaxDynamicSharedMemorySize, GEMM_SMEM);
        attr_set = true;
    }

    zero_kernel<<<(N_NODES * 64 + 255) / 256, 256>>>();
    hist_kernel<<<(N_EDGES + 255) / 256, 256>>>(dst);
    scan_kernel<<<1, 1024>>>();
    reorder_kernel<<<(N_EDGES + 255) / 256, 256>>>(src, dst, et);
    prep_b2_kernel<<<256, 256>>>(basis, loopw);
    agg_kernel<<<(N_NODES + 7) / 8, 256>>>(x, comp);
    dim3 gg(3, (N_NODES + 63) / 64);
    gemm_mma_kernel<<<gg, 256, GEMM_SMEM>>>();
    epilogue_kernel<<<(N_NODES * 32 + 255) / 256, 256>>>(x, bias, gamma, beta, out);
}